// round 16
// baseline (speedup 1.0000x reference)
#include <cuda_runtime.h>

// Problem constants
#define B_   64
#define C_   256
#define HW_  4096
#define EMB_ 512
#define BT   2                              // batches per stage warp-task
#define NTASK (C_ * (B_ / BT))              // 8192 tasks per stage
#define STG_BLOCKS (NTASK / 8)              // 1024 blocks x 8 warps

// Scratch (allocation-free rule: __device__ globals)
__device__ float g_t1[B_ * C_];
__device__ float g_t2[B_ * C_];

// ---------------------------------------------------------------------------
// Stage: out[(b0+j)*C + r] = dot(W[r], in[b0+j], LEN) + bias[r], j < BT.
// COMPILE-TIME trip count with explicit load arrays: all NIT*3 float4 loads
// are issued back-to-back (front-batched, MLP = 3*NIT per thread) before any
// FMA consumes them. This is the fix for the runtime-start loop that the
// compiler could not unroll (which serialized the DRAM fetches).
// ---------------------------------------------------------------------------
template <int LEN>
__global__ void __launch_bounds__(256) stage_kernel(
    const float* __restrict__ W,      // (C_, LEN) row-major (pre-offset)
    const float* __restrict__ invec,  // (B_, LEN)
    const float* __restrict__ bias,   // (C_,) pre-offset
    float* __restrict__ out)          // (B_, C_)
{
    constexpr int NIT = LEN / 128;    // 4 for LEN=512, 2 for LEN=256
    const int lane = threadIdx.x & 31;
    const int gw   = blockIdx.x * 8 + (threadIdx.x >> 5);   // 0 .. NTASK-1
    const int r    = gw & (C_ - 1);
    const int b0   = (gw >> 8) * BT;

    const float4* __restrict__ wrow = reinterpret_cast<const float4*>(W + (size_t)r * LEN);
    const float4* __restrict__ xin  = reinterpret_cast<const float4*>(invec + (size_t)b0 * LEN);

    // Front-batch ALL loads (independent; scoreboard overlaps the fetches).
    float4 wa[NIT], ca[NIT], cb[NIT];
    #pragma unroll
    for (int i = 0; i < NIT; i++) {
        const int k = lane + 32 * i;
        wa[i] = wrow[k];
        ca[i] = xin[k];
        cb[i] = xin[(LEN / 4) + k];
    }

    float acc0 = 0.f, acc1 = 0.f;
    #pragma unroll
    for (int i = 0; i < NIT; i++) {
        acc0 += wa[i].x * ca[i].x + wa[i].y * ca[i].y + wa[i].z * ca[i].z + wa[i].w * ca[i].w;
        acc1 += wa[i].x * cb[i].x + wa[i].y * cb[i].y + wa[i].z * cb[i].z + wa[i].w * cb[i].w;
    }
    #pragma unroll
    for (int o = 16; o > 0; o >>= 1) {
        acc0 += __shfl_down_sync(0xffffffffu, acc0, o);
        acc1 += __shfl_down_sync(0xffffffffu, acc1, o);
    }
    if (lane == 0) {
        const float bs = bias[r];
        out[(size_t)b0 * C_ + r]       = acc0 + bs;
        out[(size_t)(b0 + 1) * C_ + r] = acc1 + bs;
    }
}

// ---------------------------------------------------------------------------
// Stream kernel with inline stage 3 (R7-proven form, unchanged):
//   a       = dot(out_w[c,:], t2[b,:]) + out_b[c]
//   y[bc,:] = x[bc,:] + a
// ---------------------------------------------------------------------------
__global__ void __launch_bounds__(256) broadcast_add_kernel(
    const float* __restrict__ x,
    const float* __restrict__ out_w,   // (C_, C_)
    const float* __restrict__ out_b,   // (C_,)
    float* __restrict__ y)
{
    const int bc   = blockIdx.x;                 // 0 .. B*C-1
    const int b    = bc >> 8;
    const int c    = bc & (C_ - 1);
    const int tid  = threadIdx.x;
    const int lane = tid & 31;
    const int warp = tid >> 5;

    const float4* __restrict__ xi = reinterpret_cast<const float4*>(x) + (size_t)bc * (HW_ / 4);
    float4* __restrict__       yo = reinterpret_cast<float4*>(y)       + (size_t)bc * (HW_ / 4);

    // Streaming loads first; the dot hides beneath them.
    float4 v0 = xi[tid];
    float4 v1 = xi[tid + 256];
    float4 v2 = xi[tid + 512];
    float4 v3 = xi[tid + 768];

    float p = out_w[(size_t)c * C_ + tid] * g_t2[(size_t)b * C_ + tid];
    #pragma unroll
    for (int o = 16; o > 0; o >>= 1)
        p += __shfl_down_sync(0xffffffffu, p, o);

    __shared__ float s_part[8];
    __shared__ float s_a;
    if (lane == 0) s_part[warp] = p;
    __syncthreads();
    if (tid < 8) {
        float q = s_part[tid];
        q += __shfl_down_sync(0x000000ffu, q, 4);
        q += __shfl_down_sync(0x000000ffu, q, 2);
        q += __shfl_down_sync(0x000000ffu, q, 1);
        if (tid == 0) s_a = q + out_b[c];
    }
    __syncthreads();
    const float a = s_a;

    v0.x += a; v0.y += a; v0.z += a; v0.w += a;
    v1.x += a; v1.y += a; v1.z += a; v1.w += a;
    v2.x += a; v2.y += a; v2.z += a; v2.w += a;
    v3.x += a; v3.y += a; v3.z += a; v3.w += a;
    yo[tid]       = v0;
    yo[tid + 256] = v1;
    yo[tid + 512] = v2;
    yo[tid + 768] = v3;
}

extern "C" void kernel_launch(void* const* d_in, const int* in_sizes, int n_in,
                              void* d_out, int out_size)
{
    // metadata order: x, cond_emb, ln_gamma, ln_beta, in_proj_w, in_proj_b,
    //                 out_w, out_b, kv_w, kv_b
    const float* x         = (const float*)d_in[0];
    const float* cond_emb  = (const float*)d_in[1];
    // ln_gamma/ln_beta provably do not affect the output: softmax over the
    // size-1 KV axis is exactly 1, so q (and thus x_ln) cancels.
    const float* in_proj_w = (const float*)d_in[4];
    const float* in_proj_b = (const float*)d_in[5];
    const float* out_w     = (const float*)d_in[6];
    const float* out_b     = (const float*)d_in[7];
    const float* kv_w      = (const float*)d_in[8];
    const float* kv_b      = (const float*)d_in[9];
    float* y = (float*)d_out;

    float *t1, *t2;
    cudaGetSymbolAddress((void**)&t1, g_t1);
    cudaGetSymbolAddress((void**)&t2, g_t2);

    // Stage 1: t1[b] = kv_w[C:2C] @ ce[b] + kv_b[C:]
    stage_kernel<EMB_><<<STG_BLOCKS, 256>>>(kv_w + (size_t)C_ * EMB_, cond_emb,
                                            kv_b + C_, t1);
    // Stage 2: t2[b] = wv @ t1[b] + bv
    stage_kernel<C_><<<STG_BLOCKS, 256>>>(in_proj_w + (size_t)2 * C_ * C_, t1,
                                          in_proj_b + 2 * C_, t2);
    // Stage 3 fused into the stream kernel.
    broadcast_add_kernel<<<B_ * C_, 256>>>(x, out_w, out_b, y);
}